// round 12
// baseline (speedup 1.0000x reference)
#include <cuda_runtime.h>
#include <math.h>

#define D 128
#define NQ 7
#define NPAIR 21
#define NOFF 29   // 1 + 7 + 21 sparse offsets of A / accessed-row set
#define NSTAGE 16
#define NTHR 520  // 8 groups x 65 columns (Hermitian half-band)
#define NCOL 65
#define NGRP 8

// ---------------- device-side scratch (no runtime allocation) ----------------
__device__ float  g_Hs1[NQ][4];
__device__ float  g_Cs1[NQ][4];
__device__ float  g_Ss1[NQ][16];
__device__ float  g_Hp[NPAIR][16];
__device__ float  g_Cp[NPAIR][16];
__device__ float  g_Sp[NPAIR][256];
__device__ __align__(16) float2 g_Arow[NOFF*D];    // Arow[k][x] = A[x][x^d_k]
__device__ __align__(16) float2 g_Acol[NOFF*D];    // Acol[k][y] = conj(A[y][y^d_k])
__device__ __align__(16) float2 g_rho[D*D];
__device__ __align__(16) float2 g_st0[D*D];
__device__ __align__(16) float2 g_st1[D*D];
__device__ __align__(16) float2 g_acc[D*D];

// software grid barrier state (18 barriers/launch = even -> sense ends at 0, replay-safe)
__device__ unsigned int g_bar_count = 0;
__device__ volatile unsigned int g_bar_sense = 0;

// runtime-indexed tables (constant memory)
__constant__ int c_pi[NPAIR] = {0,0,0,0,0,0, 1,1,1,1,1, 2,2,2,2, 3,3,3, 4,4, 5};
__constant__ int c_pj[NPAIR] = {1,2,3,4,5,6, 2,3,4,5,6, 3,4,5,6, 4,5,6, 5,6, 6};
__constant__ int c_mi[NPAIR] = {64,64,64,64,64,64, 32,32,32,32,32, 16,16,16,16, 8,8,8, 4,4, 2};
__constant__ int c_mj[NPAIR] = {32,16, 8, 4, 2, 1, 16, 8, 4, 2, 1,  8, 4, 2, 1, 4,2,1, 2,1, 1};
__constant__ int c_dd[NOFF]  = {0, 64,32,16,8,4,2,1,
    96,80,72,68,66,65, 48,40,36,34,33, 24,20,18,17, 12,10,9, 6,5, 3};
// offset value -> slot index (255 = unused)
__constant__ unsigned char c_lut[128] = {
    0,7,6,28,5,27,26,255,  4,25,24,255,23,255,255,255,
    3,22,21,255,20,255,255,255,  19,255,255,255,255,255,255,255,
    2,18,17,255,16,255,255,255,  15,255,255,255,255,255,255,255,
    14,255,255,255,255,255,255,255,  255,255,255,255,255,255,255,255,
    1,13,12,255,11,255,255,255,  10,255,255,255,255,255,255,255,
    9,255,255,255,255,255,255,255,  255,255,255,255,255,255,255,255,
    8,255,255,255,255,255,255,255,  255,255,255,255,255,255,255,255,
    255,255,255,255,255,255,255,255,  255,255,255,255,255,255,255,255};

// RK4 stage schedule: s = 4t+j.  sel codes: 0=st0, 1=st1, 2=acc, 3=rho
__constant__ int   cs_in[4] = {3, 0, 1, 0};
__constant__ int   cs_sb[4] = {3, 3, 3, 2};
__constant__ int   cs_ab[4] = {3, 2, 2, 2};
__constant__ int   cs_so[4] = {0, 1, 0, 3};
__constant__ float cs_fs[4] = {0.5f, 0.5f, 1.0f, 1.f/6.f};
__constant__ float cs_fa[4] = {1.f/6.f, 1.f/3.f, 1.f/3.f, 0.f};

// compile-time tables (fold to immediates in unrolled loops)
#define DCE __host__ __device__ __forceinline__ constexpr
DCE int ct_mi(int p) { const int v[NPAIR] = {64,64,64,64,64,64, 32,32,32,32,32, 16,16,16,16, 8,8,8, 4,4, 2}; return v[p]; }
DCE int ct_mj(int p) { const int v[NPAIR] = {32,16, 8, 4, 2, 1, 16, 8, 4, 2, 1,  8, 4, 2, 1, 4,2,1, 2,1, 1}; return v[p]; }
DCE int ct_dd(int k) { const int v[NOFF]  = {0, 64,32,16,8,4,2,1,
    96,80,72,68,66,65, 48,40,36,34,33, 24,20,18,17, 12,10,9, 6,5, 3}; return v[k]; }
DCE int ct_k0(int q) { const int v[NGRP] = {0,4,8,12,16,20,23,26}; return v[q]; }
DCE int ct_k1(int q) { const int v[NGRP] = {4,8,12,16,20,23,26,29}; return v[q]; }
DCE int ct_p0(int q) { const int v[NGRP] = {0,3,6,9,12,15,17,19}; return v[q]; }
DCE int ct_p1(int q) { const int v[NGRP] = {3,6,9,12,15,17,19,21}; return v[q]; }
DCE int ct_s0(int q) { const int v[NGRP] = {0,1,2,3,4,5,6,7}; return v[q]; }
DCE int ct_s1(int q) { const int v[NGRP] = {1,2,3,4,5,6,7,7}; return v[q]; }
DCE int ct_sb(int i) { const int v[NQ] = {64,32,16,8,4,2,1}; return v[i]; }

// dynamic smem layout (bytes)
#define SM_RHO    0          // float2[29*128] = 29696  (also prep scratch)
#define SM_ACOL   29696      // float2[29*128] = 29696
#define SM_AROW   59392      // float2[32]     = 256
#define SM_PART   59648      // float2[7*65]   = 3640 (pad 4096)
#define SM_SX     63744      // float[21*64]   = 5376
#define SM_SSX    69120      // float[7*8]     = 224
#define SMEM_BYTES 69376
// prep scratch overlay (inside SM_RHO region, used only before rho staged)
#define PR_OPS    0          // float[28]
#define PR_K      128        // float[336]
#define PR_B1     1472       // float[336]
#define PR_B2     2816       // float[336]

// ---------------- buffer selection ----------------
__device__ __forceinline__ const float2* rsv(int sel) {
    if (sel == 0) return g_st0;
    if (sel == 1) return g_st1;
    if (sel == 2) return g_acc;
    return g_rho;
}
__device__ __forceinline__ float2* rsvw(int sel) {
    if (sel == 0) return g_st0;
    if (sel == 1) return g_st1;
    if (sel == 2) return g_acc;
    return g_rho;
}

// ---------------- software grid barrier (all blocks co-resident) ----------------
__device__ __forceinline__ void grid_barrier(unsigned int &sense)
{
    __threadfence();
    __syncthreads();
    if (threadIdx.x == 0) {
        sense ^= 1u;
        unsigned int a = atomicAdd(&g_bar_count, 1u);
        if (a == gridDim.x - 1) {
            g_bar_count = 0;
            __threadfence();
            g_bar_sense = sense;
        } else {
            while (g_bar_sense != sense) { }
        }
    }
    __syncthreads();
}

// ---------------- inline prep (block 0 only, parallel) ----------------
__device__ void prep_inline(int tid, char* smem,
                            const float* __restrict__ features,
                            const float* __restrict__ W1, const float* __restrict__ b1,
                            const float* __restrict__ W2, const float* __restrict__ b2,
                            const float* __restrict__ Hself, const float* __restrict__ Hcoup,
                            const float* __restrict__ rates)
{
    float* sOps = (float*)(smem + PR_OPS);
    float* sK   = (float*)(smem + PR_K);
    float* sB1  = (float*)(smem + PR_B1);
    float* sB2  = (float*)(smem + PR_B2);

    // MLP: 7 warps, lane handles hidden units l and l+32
    if (tid < 224) {
        int w = tid >> 5, l = tid & 31;
        float f0 = features[w*2+0], f1 = features[w*2+1];
        float o0 = 0.f, o1 = 0.f, o2 = 0.f, o3 = 0.f;
        #pragma unroll
        for (int t = 0; t < 2; t++) {
            int h = l + t*32;
            float v = fmaf(f0, W1[h], fmaf(f1, W1[64+h], b1[h]));
            v = fmaxf(v, 0.f);
            o0 = fmaf(v, W2[h*4+0], o0);
            o1 = fmaf(v, W2[h*4+1], o1);
            o2 = fmaf(v, W2[h*4+2], o2);
            o3 = fmaf(v, W2[h*4+3], o3);
        }
        #pragma unroll
        for (int off = 16; off; off >>= 1) {
            o0 += __shfl_xor_sync(0xFFFFFFFFu, o0, off);
            o1 += __shfl_xor_sync(0xFFFFFFFFu, o1, off);
            o2 += __shfl_xor_sync(0xFFFFFFFFu, o2, off);
            o3 += __shfl_xor_sync(0xFFFFFFFFu, o3, off);
        }
        if (l == 0) {
            sOps[w*4+0] = o0 + b2[0];
            sOps[w*4+1] = o1 + b2[1];
            sOps[w*4+2] = o2 + b2[2];
            sOps[w*4+3] = o3 + b2[3];
        }
    }
    __syncthreads();

    // singles (tid < 7)
    if (tid < NQ) {
        int i = tid;
        const float* Hs = Hself + i*4;
        float o0=sOps[i*4+0], o1=sOps[i*4+1], o2=sOps[i*4+2], o3=sOps[i*4+3];
        float G0 = o0*Hs[0] + o1*Hs[2];
        float G1 = o0*Hs[1] + o1*Hs[3];
        float G2 = o2*Hs[0] + o3*Hs[2];
        float G3 = o2*Hs[1] + o3*Hs[3];
        g_Hs1[i][0] = 2.f*G0; g_Hs1[i][1] = G1+G2; g_Hs1[i][2] = G2+G1; g_Hs1[i][3] = 2.f*G3;
        const float* rr = rates + (i*NQ+i)*16;
        float B[4];
        B[0] = sqrtf(fabsf(rr[0]))*o0;
        B[1] = sqrtf(fabsf(rr[1]))*o1;
        B[2] = sqrtf(fabsf(rr[4]))*o2;
        B[3] = sqrtf(fabsf(rr[5]))*o3;
        g_Cs1[i][0] = B[0]*B[0]+B[2]*B[2];
        g_Cs1[i][1] = B[0]*B[1]+B[2]*B[3];
        g_Cs1[i][2] = B[1]*B[0]+B[3]*B[2];
        g_Cs1[i][3] = B[1]*B[1]+B[3]*B[3];
        for (int a=0;a<2;a++)
          for (int b=0;b<2;b++)
            for (int ap=0;ap<2;ap++)
              for (int bp=0;bp<2;bp++)
                g_Ss1[i][((a*2+b)*2+ap)*2+bp] = B[a*2+ap]*B[b*2+bp];
    }

    // pair K/B1/B2 entries (tid < 336)
    if (tid < NPAIR*16) {
        int p = tid >> 4, uv = tid & 15;
        int i = c_pi[p], j = c_pj[p];
        int u = uv >> 2, v = uv & 3;
        float kv = sOps[i*4+(u>>1)*2+(v>>1)] * sOps[j*4+(u&1)*2+(v&1)];
        sK[p*16+uv]  = kv;
        sB1[p*16+uv] = sqrtf(fabsf(rates[(i*NQ+j)*16 + uv])) * kv;
        int us = ((u&1)<<1)|(u>>1), vs = ((v&1)<<1)|(v>>1);
        float kv2 = sOps[j*4+(us>>1)*2+(vs>>1)] * sOps[i*4+(us&1)*2+(vs&1)];
        sB2[p*16+uv] = sqrtf(fabsf(rates[(j*NQ+i)*16 + us*4+vs])) * kv2;
    }
    __syncthreads();

    // Hp, Cp (tid < 336)
    if (tid < NPAIR*16) {
        int p = tid >> 4, uv = tid & 15;
        int u = uv >> 2, v = uv & 3;
        int i = c_pi[p], j = c_pj[p];
        const float* Hc = Hcoup + (i*NQ+j)*16;
        float s = 0.f, c = 0.f;
        #pragma unroll
        for (int k = 0; k < 4; k++) {
            s += sK[p*16+u*4+k]*Hc[k*4+v] + sK[p*16+v*4+k]*Hc[k*4+u];
            c += sB1[p*16+k*4+u]*sB1[p*16+k*4+v] + sB2[p*16+k*4+u]*sB2[p*16+k*4+v];
        }
        g_Hp[p][uv] = s;
        g_Cp[p][uv] = c;
    }

    // Sp table (all threads)
    for (int e = tid; e < NPAIR*256; e += NTHR) {
        int p = e >> 8, r = e & 255;
        int u = (r>>6)&3, v = (r>>4)&3, ap = (r>>2)&3, bp = r&3;
        g_Sp[p][r] = sB1[p*16+u*4+ap]*sB1[p*16+v*4+bp] + sB2[p*16+u*4+ap]*sB2[p*16+v*4+bp];
    }
}

// ---------------- templated per-q stage compute (rhs element (x,y)) ----------------
template<int Q>
__device__ __forceinline__ void comp_stage(const float2* __restrict__ sRho,
                                           const float2* __restrict__ sAcol,
                                           const float2* __restrict__ sArow,
                                           const float*  __restrict__ sSx,
                                           const float*  __restrict__ sSsx,
                                           int x, int y, float& re, float& im)
{
    // sparse dense part
    #pragma unroll
    for (int k = ct_k0(Q); k < ct_k1(Q); k++) {
        const int d = ct_dd(k);
        float2 c1 = sArow[k];
        float2 r1 = sRho[(k<<7)+y];
        re = fmaf(c1.x, r1.x, re); re = fmaf(-c1.y, r1.y, re);
        im = fmaf(c1.x, r1.y, im); im = fmaf( c1.y, r1.x, im);
        float2 c2 = sAcol[(k<<7)+y];
        float2 r2 = sRho[y ^ d];
        re = fmaf(c2.x, r2.x, re); re = fmaf(-c2.y, r2.y, re);
        im = fmaf(c2.x, r2.y, im); im = fmaf( c2.y, r2.x, im);
    }
    // pair superoperators
    #pragma unroll
    for (int p = ct_p0(Q); p < ct_p1(Q); p++) {
        const int mi = ct_mi(p), mj = ct_mj(p), m = mi|mj;
        int yl = (((y&mi)!=0)<<1)|((y&mj)!=0);
        int xm = x & m;
        int xr0 = ((int)c_lut[xm])    << 7;
        int xr1 = ((int)c_lut[xm^mj]) << 7;
        int xr2 = ((int)c_lut[xm^mi]) << 7;
        int xr3 = ((int)c_lut[xm^m])  << 7;
        int y0 = y & ~m;
        int yc0 = y0, yc1 = y0 + mj, yc2 = y0 + mi, yc3 = y0 + m;
        const float4* Sp = reinterpret_cast<const float4*>(sSx + p*64 + yl*16);
        float4 s0 = Sp[0], s1 = Sp[1], s2 = Sp[2], s3 = Sp[3];
        float2 r;
        r = sRho[xr0+yc0]; re = fmaf(s0.x,r.x,re); im = fmaf(s0.x,r.y,im);
        r = sRho[xr0+yc1]; re = fmaf(s0.y,r.x,re); im = fmaf(s0.y,r.y,im);
        r = sRho[xr0+yc2]; re = fmaf(s0.z,r.x,re); im = fmaf(s0.z,r.y,im);
        r = sRho[xr0+yc3]; re = fmaf(s0.w,r.x,re); im = fmaf(s0.w,r.y,im);
        r = sRho[xr1+yc0]; re = fmaf(s1.x,r.x,re); im = fmaf(s1.x,r.y,im);
        r = sRho[xr1+yc1]; re = fmaf(s1.y,r.x,re); im = fmaf(s1.y,r.y,im);
        r = sRho[xr1+yc2]; re = fmaf(s1.z,r.x,re); im = fmaf(s1.z,r.y,im);
        r = sRho[xr1+yc3]; re = fmaf(s1.w,r.x,re); im = fmaf(s1.w,r.y,im);
        r = sRho[xr2+yc0]; re = fmaf(s2.x,r.x,re); im = fmaf(s2.x,r.y,im);
        r = sRho[xr2+yc1]; re = fmaf(s2.y,r.x,re); im = fmaf(s2.y,r.y,im);
        r = sRho[xr2+yc2]; re = fmaf(s2.z,r.x,re); im = fmaf(s2.z,r.y,im);
        r = sRho[xr2+yc3]; re = fmaf(s2.w,r.x,re); im = fmaf(s2.w,r.y,im);
        r = sRho[xr3+yc0]; re = fmaf(s3.x,r.x,re); im = fmaf(s3.x,r.y,im);
        r = sRho[xr3+yc1]; re = fmaf(s3.y,r.x,re); im = fmaf(s3.y,r.y,im);
        r = sRho[xr3+yc2]; re = fmaf(s3.z,r.x,re); im = fmaf(s3.z,r.y,im);
        r = sRho[xr3+yc3]; re = fmaf(s3.w,r.x,re); im = fmaf(s3.w,r.y,im);
    }
    // single-site superoperators
    #pragma unroll
    for (int i = ct_s0(Q); i < ct_s1(Q); i++) {
        const int mi = ct_sb(i);
        int yl = (y&mi)!=0;
        int xmi = x & mi;
        int xb0 = ((int)c_lut[xmi])    << 7;
        int xb1 = ((int)c_lut[xmi^mi]) << 7;
        int y0 = y & ~mi;
        const float* Ss = sSsx + i*8 + yl*4;
        float s0 = Ss[0], s1 = Ss[1], s2 = Ss[2], s3 = Ss[3];
        float2 r;
        r = sRho[xb0 + y0];      re = fmaf(s0,r.x,re); im = fmaf(s0,r.y,im);
        r = sRho[xb0 + y0 + mi]; re = fmaf(s1,r.x,re); im = fmaf(s1,r.y,im);
        r = sRho[xb1 + y0];      re = fmaf(s2,r.x,re); im = fmaf(s2,r.y,im);
        r = sRho[xb1 + y0 + mi]; re = fmaf(s3,r.x,re); im = fmaf(s3,r.y,im);
    }
}

// ---------------- the single fused kernel ----------------
__global__ void __launch_bounds__(NTHR, 1)
solve_kernel(float* __restrict__ out, const float* __restrict__ t_eval,
             const float* __restrict__ features,
             const float* __restrict__ W1, const float* __restrict__ b1,
             const float* __restrict__ W2, const float* __restrict__ b2,
             const float* __restrict__ Hself, const float* __restrict__ Hcoup,
             const float* __restrict__ rates, const float* __restrict__ rho0)
{
    extern __shared__ __align__(16) char smem[];
    float2* sRho   = (float2*)(smem + SM_RHO);
    float2* sAcol  = (float2*)(smem + SM_ACOL);
    float2* sArow  = (float2*)(smem + SM_AROW);
    float2* sPart  = (float2*)(smem + SM_PART);
    float*  sSx    = (float*)(smem + SM_SX);
    float*  sSsx   = (float*)(smem + SM_SSX);

    int x   = blockIdx.x;
    int tid = threadIdx.x;
    int q   = tid / NCOL;          // 0..7
    int jj  = tid - q*NCOL;        // 0..64 (wrapped column offset)
    int y   = (x + jj) & 127;      // actual column
    unsigned int sense = 0;

    // ---- phase A: prep (block 0 only) ----
    if (x == 0)
        prep_inline(tid, smem, features, W1, b1, W2, b2, Hself, Hcoup, rates);
    grid_barrier(sense);

    // ---- phase B: build A sparse tables + init rho/out0 (each block = its row) ----
    if (tid < D) {
        int yb = tid;
        int d = x ^ yb;
        float Hv = 0.f, Mv = 0.f;
        #pragma unroll
        for (int i = 0; i < NQ; i++) {
            int mi = 1<<(6-i);
            if ((d & (127 ^ mi)) == 0) {
                int xl = (x>>(6-i))&1, yl = (yb>>(6-i))&1;
                Hv += g_Hs1[i][xl*2+yl];
                Mv += g_Cs1[i][xl*2+yl];
            }
        }
        #pragma unroll
        for (int p = 0; p < NPAIR; p++) {
            int mi = c_mi[p], mj = c_mj[p];
            if ((d & (127 ^ (mi|mj))) == 0) {
                int xl = (((x&mi)!=0)<<1)|((x&mj)!=0);
                int yl = (((yb&mi)!=0)<<1)|((yb&mj)!=0);
                Hv += g_Hp[p][xl*4+yl];
                Mv += g_Cp[p][xl*4+yl];
            }
        }
        int k = c_lut[d];
        if (k < NOFF) {
            g_Arow[(k<<7)+x] = make_float2(-0.5f*Mv, -Hv);
            g_Acol[(k<<7)+x] = make_float2(-0.5f*Mv,  Hv);
        }
        float v = rho0[(x<<7)+yb];
        g_rho[(x<<7)+yb] = make_float2(v, 0.f);
        out[(x<<7)+yb] = v;
    }
    grid_barrier(sense);

    // ---- phase C: stage invariant tables ----
    {
        const float4* gv = (const float4*)g_Acol;
        float4* sv = (float4*)sAcol;
        for (int t = tid; t < NOFF*64; t += NTHR) sv[t] = __ldcg(&gv[t]);
    }
    if (tid < NOFF) sArow[tid] = __ldcg(&g_Arow[(tid<<7) + x]);
    for (int t = tid; t < NPAIR*64; t += NTHR) {
        int p = t >> 6;
        int mi = c_mi[p], mj = c_mj[p];
        int xl = (((x&mi)!=0)<<1)|((x&mj)!=0);
        sSx[t] = __ldcg(&g_Sp[p][xl*64 + (t & 63)]);
    }
    if (tid >= NTHR-NQ*8) {
        int t = tid - (NTHR-NQ*8);
        int i = t >> 3;
        int mi = 1<<(6-i);
        int xl = (x & mi) != 0;
        sSsx[t] = __ldcg(&g_Ss1[i][xl*8 + (t & 7)]);
    }

    // write-ownership guard: j=64 pairs are owned by blocks x<64 (single writer)
    bool act = (jj < 64) || (x < 64);

    // ---- phase D: 16 RK4 stages (Hermitian half-band per block) ----
    for (int s = 0; s < NSTAGE; s++) {
        int j = s & 3, step = s >> 2;
        const float2* in = rsv(cs_in[j]);

        {
            const float4* inv = (const float4*)in;
            float4* srv = (float4*)sRho;
            for (int t = tid; t < NOFF*64; t += NTHR) {
                int k = t >> 6, c4 = t & 63;
                srv[t] = __ldcg(&inv[((x ^ c_dd[k])<<6) + c4]);
            }
        }
        __syncthreads();

        float re = 0.f, im = 0.f;
        switch (q) {
            case 0:  comp_stage<0>(sRho, sAcol, sArow, sSx, sSsx, x, y, re, im); break;
            case 1:  comp_stage<1>(sRho, sAcol, sArow, sSx, sSsx, x, y, re, im); break;
            case 2:  comp_stage<2>(sRho, sAcol, sArow, sSx, sSsx, x, y, re, im); break;
            case 3:  comp_stage<3>(sRho, sAcol, sArow, sSx, sSsx, x, y, re, im); break;
            case 4:  comp_stage<4>(sRho, sAcol, sArow, sSx, sSsx, x, y, re, im); break;
            case 5:  comp_stage<5>(sRho, sAcol, sArow, sSx, sSsx, x, y, re, im); break;
            case 6:  comp_stage<6>(sRho, sAcol, sArow, sSx, sSsx, x, y, re, im); break;
            default: comp_stage<7>(sRho, sAcol, sArow, sSx, sSsx, x, y, re, im); break;
        }

        if (q != 0) sPart[(q-1)*NCOL + jj] = make_float2(re, im);
        __syncthreads();
        if (q == 0) {
            #pragma unroll
            for (int g = 0; g < NGRP-1; g++) {
                float2 pp = sPart[g*NCOL + jj];
                re += pp.x; im += pp.y;
            }
            if (act) {
                int idx1 = (x<<7) + y;
                int idx2 = (y<<7) + x;
                float dt = __ldg(&t_eval[step+1]) - __ldg(&t_eval[step]);
                const float2* sb = rsv(cs_sb[j]);
                float2* so = rsvw(cs_so[j]);
                float cs = cs_fs[j]*dt;
                float2 sv = __ldcg(&sb[idx1]);
                float2 ov = make_float2(fmaf(cs, re, sv.x), fmaf(cs, im, sv.y));
                so[idx1] = ov;
                if (jj) so[idx2] = make_float2(ov.x, -ov.y);
                if (j == 3) {
                    out[(step+1)*D*D + idx1] = ov.x;
                    if (jj) out[(step+1)*D*D + idx2] = ov.x;
                }
                float fa = cs_fa[j];
                if (fa != 0.f) {
                    const float2* ab = rsv(cs_ab[j]);
                    float2 av = __ldcg(&ab[idx1]);
                    float ca = fa*dt;
                    float2 acv = make_float2(fmaf(ca, re, av.x), fmaf(ca, im, av.y));
                    g_acc[idx1] = acv;
                    if (jj) g_acc[idx2] = make_float2(acv.x, -acv.y);
                }
            }
        }
        grid_barrier(sense);   // 18 barriers total (even): sense ends 0, replay-safe
    }
}

// ---------------- launcher ----------------
extern "C" void kernel_launch(void* const* d_in, const int* in_sizes, int n_in,
                              void* d_out, int out_size)
{
    const float *features=0, *t_eval=0, *W1=0, *b1=0, *W2=0, *b2=0;
    const float *Hself=0, *Hcoup=0, *rates=0, *rho0=0;
    int n784 = 0;
    for (int i = 0; i < n_in; i++) {
        const float* p = (const float*)d_in[i];
        switch (in_sizes[i]) {
            case 14:    features = p; break;
            case 5:     t_eval   = p; break;
            case 128:   W1       = p; break;
            case 64:    b1       = p; break;
            case 256:   W2       = p; break;
            case 4:     b2       = p; break;
            case 28:    Hself    = p; break;
            case 784:   if (n784++ == 0) Hcoup = p; else rates = p; break;
            case 16384: rho0     = p; break;
            default: break;
        }
    }
    if (!features) features = (const float*)d_in[0];
    if (!t_eval)   t_eval   = (const float*)d_in[1];
    if (!W1)       W1       = (const float*)d_in[2];
    if (!b1)       b1       = (const float*)d_in[3];
    if (!W2)       W2       = (const float*)d_in[4];
    if (!b2)       b2       = (const float*)d_in[5];
    if (!Hself)    Hself    = (const float*)d_in[6];
    if (!Hcoup)    Hcoup    = (const float*)d_in[7];
    if (!rates)    rates    = (const float*)d_in[8];
    if (!rho0)     rho0     = (const float*)d_in[9];

    float* out = (float*)d_out;   // float32 real output, (5,128,128)

    static int attrDone = 0;
    if (!attrDone) {
        cudaFuncSetAttribute(solve_kernel, cudaFuncAttributeMaxDynamicSharedMemorySize, SMEM_BYTES);
        attrDone = 1;
    }

    solve_kernel<<<D, NTHR, SMEM_BYTES>>>(out, t_eval, features, W1, b1, W2, b2,
                                          Hself, Hcoup, rates, rho0);
    (void)out_size;
}

// round 13
// speedup vs baseline: 1.0845x; 1.0845x over previous
#include <cuda_runtime.h>
#include <math.h>

#define D 128
#define NQ 7
#define NPAIR 21
#define NOFF 29
#define NSTAGE 16
#define NTHR 640
#define NCOL 64
#define NGRP 10

// ---------------- device-side scratch (no runtime allocation) ----------------
__device__ float  g_Hs1[NQ][4];
__device__ float  g_Cs1[NQ][4];
__device__ float  g_Ss1[NQ][16];
__device__ float  g_Hp[NPAIR][16];
__device__ float  g_Cp[NPAIR][16];
__device__ float  g_Sp[NPAIR][256];
__device__ __align__(16) float2 g_Arow[NOFF*D];    // Arow[k][x] = A[x][x^d_k]
__device__ __align__(16) float2 g_Acol[NOFF*D];    // Acol[k][y] = conj(A[y][y^d_k])
__device__ __align__(16) float2 g_rho[D*D];
__device__ __align__(16) float2 g_st0[D*D];
__device__ __align__(16) float2 g_st1[D*D];
__device__ __align__(16) float2 g_acc[D*D];

// software grid barrier (18 barriers/launch = even -> sense ends 0, replay-safe)
__device__ unsigned int g_bar_count = 0;
__device__ volatile unsigned int g_bar_sense = 0;

// runtime-indexed tables
__constant__ int c_pi[NPAIR] = {0,0,0,0,0,0, 1,1,1,1,1, 2,2,2,2, 3,3,3, 4,4, 5};
__constant__ int c_pj[NPAIR] = {1,2,3,4,5,6, 2,3,4,5,6, 3,4,5,6, 4,5,6, 5,6, 6};
__constant__ int c_mi[NPAIR] = {64,64,64,64,64,64, 32,32,32,32,32, 16,16,16,16, 8,8,8, 4,4, 2};
__constant__ int c_mj[NPAIR] = {32,16, 8, 4, 2, 1, 16, 8, 4, 2, 1,  8, 4, 2, 1, 4,2,1, 2,1, 1};
__constant__ int c_dd[NOFF]  = {0, 64,32,16,8,4,2,1,
    96,80,72,68,66,65, 48,40,36,34,33, 24,20,18,17, 12,10,9, 6,5, 3};
__constant__ unsigned char c_lut[128] = {
    0,7,6,28,5,27,26,255,  4,25,24,255,23,255,255,255,
    3,22,21,255,20,255,255,255,  19,255,255,255,255,255,255,255,
    2,18,17,255,16,255,255,255,  15,255,255,255,255,255,255,255,
    14,255,255,255,255,255,255,255,  255,255,255,255,255,255,255,255,
    1,13,12,255,11,255,255,255,  10,255,255,255,255,255,255,255,
    9,255,255,255,255,255,255,255,  255,255,255,255,255,255,255,255,
    8,255,255,255,255,255,255,255,  255,255,255,255,255,255,255,255,
    255,255,255,255,255,255,255,255,  255,255,255,255,255,255,255,255};

// RK4 stage schedule: s = 4t+j.  sel: 0=st0, 1=st1, 2=acc, 3=rho
__constant__ int   cs_in[4] = {3, 0, 1, 0};
__constant__ int   cs_sb[4] = {3, 3, 3, 2};
__constant__ int   cs_ab[4] = {3, 2, 2, 2};
__constant__ int   cs_so[4] = {0, 1, 0, 3};
__constant__ float cs_fs[4] = {0.5f, 0.5f, 1.0f, 1.f/6.f};
__constant__ float cs_fa[4] = {1.f/6.f, 1.f/3.f, 1.f/3.f, 0.f};

// compile-time tables (fold to immediates in unrolled loops)
#define DCE __host__ __device__ __forceinline__ constexpr
DCE int ct_mi(int p) { const int v[NPAIR] = {64,64,64,64,64,64, 32,32,32,32,32, 16,16,16,16, 8,8,8, 4,4, 2}; return v[p]; }
DCE int ct_mj(int p) { const int v[NPAIR] = {32,16, 8, 4, 2, 1, 16, 8, 4, 2, 1,  8, 4, 2, 1, 4,2,1, 2,1, 1}; return v[p]; }
DCE int ct_dd(int k) { const int v[NOFF]  = {0, 64,32,16,8,4,2,1,
    96,80,72,68,66,65, 48,40,36,34,33, 24,20,18,17, 12,10,9, 6,5, 3}; return v[k]; }
// 10-way split: k {3x7,4,4,0}, p {2x9,3}, s {1x7,0,0,0}
DCE int ct_k0(int q) { const int v[NGRP] = {0,3,6,9,12,15,18,21,25,29}; return v[q]; }
DCE int ct_k1(int q) { const int v[NGRP] = {3,6,9,12,15,18,21,25,29,29}; return v[q]; }
DCE int ct_p0(int q) { const int v[NGRP] = {0,2,4,6,8,10,12,14,16,18}; return v[q]; }
DCE int ct_p1(int q) { const int v[NGRP] = {2,4,6,8,10,12,14,16,18,21}; return v[q]; }
DCE int ct_s0(int q) { const int v[NGRP] = {0,1,2,3,4,5,6,7,7,7}; return v[q]; }
DCE int ct_s1(int q) { const int v[NGRP] = {1,2,3,4,5,6,7,7,7,7}; return v[q]; }
DCE int ct_sb(int i) { const int v[NQ] = {64,32,16,8,4,2,1}; return v[i]; }

// ---- smem layout: NORMAL blocks (x < 128) ----
#define SM_RHO    0          // float2[29*128] = 29696  (also prep scratch)
#define SM_ACOL   29696      // float2[29*128] = 29696
#define SM_AROW   59392      // float2[32]     = 256
#define SM_PART   59648      // float2[9*64]   = 4608
#define SM_SX     64256      // float[21*64]   = 5376
#define SM_SSX    69632      // float[7*8]     = 224
// ---- smem layout: SPECIAL block (x == 128) ----
#define BF_RHO    0          // float2[128*128] = 131072
#define BF_AROW   131072     // float2[29*128]  = 29696
#define BF_ACOL   160768     // float2[29*128]  = 29696
#define BF_SP     190464     // float[21*256]   = 21504
#define BF_SS     211968     // float[7*16]     = 448
#define BF_PART   212416     // float2[9*64]    = 4608
#define SMEM_BYTES 217088
// prep scratch overlay (inside SM_RHO, block 0 only, before rho staged)
#define PR_OPS    0
#define PR_K      128
#define PR_B1     1472
#define PR_B2     2816

// ---------------- buffer selection ----------------
__device__ __forceinline__ const float2* rsv(int sel) {
    if (sel == 0) return g_st0;
    if (sel == 1) return g_st1;
    if (sel == 2) return g_acc;
    return g_rho;
}
__device__ __forceinline__ float2* rsvw(int sel) {
    if (sel == 0) return g_st0;
    if (sel == 1) return g_st1;
    if (sel == 2) return g_acc;
    return g_rho;
}

// ---------------- grid barrier ----------------
__device__ __forceinline__ void grid_barrier(unsigned int &sense)
{
    __threadfence();
    __syncthreads();
    if (threadIdx.x == 0) {
        sense ^= 1u;
        unsigned int a = atomicAdd(&g_bar_count, 1u);
        if (a == gridDim.x - 1) {
            g_bar_count = 0;
            __threadfence();
            g_bar_sense = sense;
        } else {
            while (g_bar_sense != sense) { }
        }
    }
    __syncthreads();
}

// ---------------- inline prep (block 0 only, parallel) ----------------
__device__ void prep_inline(int tid, char* smem,
                            const float* __restrict__ features,
                            const float* __restrict__ W1, const float* __restrict__ b1,
                            const float* __restrict__ W2, const float* __restrict__ b2,
                            const float* __restrict__ Hself, const float* __restrict__ Hcoup,
                            const float* __restrict__ rates)
{
    float* sOps = (float*)(smem + PR_OPS);
    float* sK   = (float*)(smem + PR_K);
    float* sB1  = (float*)(smem + PR_B1);
    float* sB2  = (float*)(smem + PR_B2);

    if (tid < 224) {
        int w = tid >> 5, l = tid & 31;
        float f0 = features[w*2+0], f1 = features[w*2+1];
        float o0 = 0.f, o1 = 0.f, o2 = 0.f, o3 = 0.f;
        #pragma unroll
        for (int t = 0; t < 2; t++) {
            int h = l + t*32;
            float v = fmaf(f0, W1[h], fmaf(f1, W1[64+h], b1[h]));
            v = fmaxf(v, 0.f);
            o0 = fmaf(v, W2[h*4+0], o0);
            o1 = fmaf(v, W2[h*4+1], o1);
            o2 = fmaf(v, W2[h*4+2], o2);
            o3 = fmaf(v, W2[h*4+3], o3);
        }
        #pragma unroll
        for (int off = 16; off; off >>= 1) {
            o0 += __shfl_xor_sync(0xFFFFFFFFu, o0, off);
            o1 += __shfl_xor_sync(0xFFFFFFFFu, o1, off);
            o2 += __shfl_xor_sync(0xFFFFFFFFu, o2, off);
            o3 += __shfl_xor_sync(0xFFFFFFFFu, o3, off);
        }
        if (l == 0) {
            sOps[w*4+0] = o0 + b2[0];
            sOps[w*4+1] = o1 + b2[1];
            sOps[w*4+2] = o2 + b2[2];
            sOps[w*4+3] = o3 + b2[3];
        }
    }
    __syncthreads();

    if (tid < NQ) {
        int i = tid;
        const float* Hs = Hself + i*4;
        float o0=sOps[i*4+0], o1=sOps[i*4+1], o2=sOps[i*4+2], o3=sOps[i*4+3];
        float G0 = o0*Hs[0] + o1*Hs[2];
        float G1 = o0*Hs[1] + o1*Hs[3];
        float G2 = o2*Hs[0] + o3*Hs[2];
        float G3 = o2*Hs[1] + o3*Hs[3];
        g_Hs1[i][0] = 2.f*G0; g_Hs1[i][1] = G1+G2; g_Hs1[i][2] = G2+G1; g_Hs1[i][3] = 2.f*G3;
        const float* rr = rates + (i*NQ+i)*16;
        float B[4];
        B[0] = sqrtf(fabsf(rr[0]))*o0;
        B[1] = sqrtf(fabsf(rr[1]))*o1;
        B[2] = sqrtf(fabsf(rr[4]))*o2;
        B[3] = sqrtf(fabsf(rr[5]))*o3;
        g_Cs1[i][0] = B[0]*B[0]+B[2]*B[2];
        g_Cs1[i][1] = B[0]*B[1]+B[2]*B[3];
        g_Cs1[i][2] = B[1]*B[0]+B[3]*B[2];
        g_Cs1[i][3] = B[1]*B[1]+B[3]*B[3];
        for (int a=0;a<2;a++)
          for (int b=0;b<2;b++)
            for (int ap=0;ap<2;ap++)
              for (int bp=0;bp<2;bp++)
                g_Ss1[i][((a*2+b)*2+ap)*2+bp] = B[a*2+ap]*B[b*2+bp];
    }

    if (tid < NPAIR*16) {
        int p = tid >> 4, uv = tid & 15;
        int i = c_pi[p], j = c_pj[p];
        int u = uv >> 2, v = uv & 3;
        float kv = sOps[i*4+(u>>1)*2+(v>>1)] * sOps[j*4+(u&1)*2+(v&1)];
        sK[p*16+uv]  = kv;
        sB1[p*16+uv] = sqrtf(fabsf(rates[(i*NQ+j)*16 + uv])) * kv;
        int us = ((u&1)<<1)|(u>>1), vs = ((v&1)<<1)|(v>>1);
        float kv2 = sOps[j*4+(us>>1)*2+(vs>>1)] * sOps[i*4+(us&1)*2+(vs&1)];
        sB2[p*16+uv] = sqrtf(fabsf(rates[(j*NQ+i)*16 + us*4+vs])) * kv2;
    }
    __syncthreads();

    if (tid < NPAIR*16) {
        int p = tid >> 4, uv = tid & 15;
        int u = uv >> 2, v = uv & 3;
        int i = c_pi[p], j = c_pj[p];
        const float* Hc = Hcoup + (i*NQ+j)*16;
        float s = 0.f, c = 0.f;
        #pragma unroll
        for (int k = 0; k < 4; k++) {
            s += sK[p*16+u*4+k]*Hc[k*4+v] + sK[p*16+v*4+k]*Hc[k*4+u];
            c += sB1[p*16+k*4+u]*sB1[p*16+k*4+v] + sB2[p*16+k*4+u]*sB2[p*16+k*4+v];
        }
        g_Hp[p][uv] = s;
        g_Cp[p][uv] = c;
    }

    for (int e = tid; e < NPAIR*256; e += NTHR) {
        int p = e >> 8, r = e & 255;
        int u = (r>>6)&3, v = (r>>4)&3, ap = (r>>2)&3, bp = r&3;
        g_Sp[p][r] = sB1[p*16+u*4+ap]*sB1[p*16+v*4+bp] + sB2[p*16+u*4+ap]*sB2[p*16+v*4+bp];
    }
}

// ---------------- slot-indexed compute (normal blocks) ----------------
template<int Q>
__device__ __forceinline__ void comp_stage(const float2* __restrict__ sRho,
                                           const float2* __restrict__ sAcol,
                                           const float2* __restrict__ sArow,
                                           const float*  __restrict__ sSx,
                                           const float*  __restrict__ sSsx,
                                           int x, int y, float& re, float& im)
{
    #pragma unroll
    for (int k = ct_k0(Q); k < ct_k1(Q); k++) {
        const int d = ct_dd(k);
        float2 c1 = sArow[k];
        float2 r1 = sRho[(k<<7)+y];
        re = fmaf(c1.x, r1.x, re); re = fmaf(-c1.y, r1.y, re);
        im = fmaf(c1.x, r1.y, im); im = fmaf( c1.y, r1.x, im);
        float2 c2 = sAcol[(k<<7)+y];
        float2 r2 = sRho[y ^ d];
        re = fmaf(c2.x, r2.x, re); re = fmaf(-c2.y, r2.y, re);
        im = fmaf(c2.x, r2.y, im); im = fmaf( c2.y, r2.x, im);
    }
    #pragma unroll
    for (int p = ct_p0(Q); p < ct_p1(Q); p++) {
        const int mi = ct_mi(p), mj = ct_mj(p), m = mi|mj;
        int yl = (((y&mi)!=0)<<1)|((y&mj)!=0);
        int xm = x & m;
        int xr0 = ((int)c_lut[xm])    << 7;
        int xr1 = ((int)c_lut[xm^mj]) << 7;
        int xr2 = ((int)c_lut[xm^mi]) << 7;
        int xr3 = ((int)c_lut[xm^m])  << 7;
        int y0 = y & ~m;
        int yc0 = y0, yc1 = y0 + mj, yc2 = y0 + mi, yc3 = y0 + m;
        const float4* Sp = reinterpret_cast<const float4*>(sSx + p*64 + yl*16);
        float4 s0 = Sp[0], s1 = Sp[1], s2 = Sp[2], s3 = Sp[3];
        float2 r;
        r = sRho[xr0+yc0]; re = fmaf(s0.x,r.x,re); im = fmaf(s0.x,r.y,im);
        r = sRho[xr0+yc1]; re = fmaf(s0.y,r.x,re); im = fmaf(s0.y,r.y,im);
        r = sRho[xr0+yc2]; re = fmaf(s0.z,r.x,re); im = fmaf(s0.z,r.y,im);
        r = sRho[xr0+yc3]; re = fmaf(s0.w,r.x,re); im = fmaf(s0.w,r.y,im);
        r = sRho[xr1+yc0]; re = fmaf(s1.x,r.x,re); im = fmaf(s1.x,r.y,im);
        r = sRho[xr1+yc1]; re = fmaf(s1.y,r.x,re); im = fmaf(s1.y,r.y,im);
        r = sRho[xr1+yc2]; re = fmaf(s1.z,r.x,re); im = fmaf(s1.z,r.y,im);
        r = sRho[xr1+yc3]; re = fmaf(s1.w,r.x,re); im = fmaf(s1.w,r.y,im);
        r = sRho[xr2+yc0]; re = fmaf(s2.x,r.x,re); im = fmaf(s2.x,r.y,im);
        r = sRho[xr2+yc1]; re = fmaf(s2.y,r.x,re); im = fmaf(s2.y,r.y,im);
        r = sRho[xr2+yc2]; re = fmaf(s2.z,r.x,re); im = fmaf(s2.z,r.y,im);
        r = sRho[xr2+yc3]; re = fmaf(s2.w,r.x,re); im = fmaf(s2.w,r.y,im);
        r = sRho[xr3+yc0]; re = fmaf(s3.x,r.x,re); im = fmaf(s3.x,r.y,im);
        r = sRho[xr3+yc1]; re = fmaf(s3.y,r.x,re); im = fmaf(s3.y,r.y,im);
        r = sRho[xr3+yc2]; re = fmaf(s3.z,r.x,re); im = fmaf(s3.z,r.y,im);
        r = sRho[xr3+yc3]; re = fmaf(s3.w,r.x,re); im = fmaf(s3.w,r.y,im);
    }
    #pragma unroll
    for (int i = ct_s0(Q); i < ct_s1(Q); i++) {
        const int mi = ct_sb(i);
        int yl = (y&mi)!=0;
        int xmi = x & mi;
        int xb0 = ((int)c_lut[xmi])    << 7;
        int xb1 = ((int)c_lut[xmi^mi]) << 7;
        int y0 = y & ~mi;
        const float* Ss = sSsx + i*8 + yl*4;
        float s0 = Ss[0], s1 = Ss[1], s2 = Ss[2], s3 = Ss[3];
        float2 r;
        r = sRho[xb0 + y0];      re = fmaf(s0,r.x,re); im = fmaf(s0,r.y,im);
        r = sRho[xb0 + y0 + mi]; re = fmaf(s1,r.x,re); im = fmaf(s1,r.y,im);
        r = sRho[xb1 + y0];      re = fmaf(s2,r.x,re); im = fmaf(s2,r.y,im);
        r = sRho[xb1 + y0 + mi]; re = fmaf(s3,r.x,re); im = fmaf(s3,r.y,im);
    }
}

// ---------------- natural-indexed compute (special block) ----------------
template<int Q>
__device__ __forceinline__ void comp_full(const float2* __restrict__ sRhoF,
                                          const float2* __restrict__ sArowF,
                                          const float2* __restrict__ sAcolF,
                                          const float*  __restrict__ sSpF,
                                          const float*  __restrict__ sSsF,
                                          int x, int y, float& re, float& im)
{
    #pragma unroll
    for (int k = ct_k0(Q); k < ct_k1(Q); k++) {
        const int d = ct_dd(k);
        float2 c1 = sArowF[(k<<7)+x];
        float2 r1 = sRhoF[((x^d)<<7)+y];
        re = fmaf(c1.x, r1.x, re); re = fmaf(-c1.y, r1.y, re);
        im = fmaf(c1.x, r1.y, im); im = fmaf( c1.y, r1.x, im);
        float2 c2 = sAcolF[(k<<7)+y];
        float2 r2 = sRhoF[(x<<7)+(y^d)];
        re = fmaf(c2.x, r2.x, re); re = fmaf(-c2.y, r2.y, re);
        im = fmaf(c2.x, r2.y, im); im = fmaf( c2.y, r2.x, im);
    }
    #pragma unroll
    for (int p = ct_p0(Q); p < ct_p1(Q); p++) {
        const int mi = ct_mi(p), mj = ct_mj(p), m = mi|mj;
        int xl = (((x&mi)!=0)<<1)|((x&mj)!=0);
        int yl = (((y&mi)!=0)<<1)|((y&mj)!=0);
        int xb = (x & ~m) << 7;
        int xr0 = xb, xr1 = xb + (mj<<7), xr2 = xb + (mi<<7), xr3 = xb + (m<<7);
        int y0 = y & ~m;
        int yc0 = y0, yc1 = y0 + mj, yc2 = y0 + mi, yc3 = y0 + m;
        const float4* Sp = reinterpret_cast<const float4*>(sSpF + ((p*4+xl)*4+yl)*16);
        float4 s0 = Sp[0], s1 = Sp[1], s2 = Sp[2], s3 = Sp[3];
        float2 r;
        r = sRhoF[xr0+yc0]; re = fmaf(s0.x,r.x,re); im = fmaf(s0.x,r.y,im);
        r = sRhoF[xr0+yc1]; re = fmaf(s0.y,r.x,re); im = fmaf(s0.y,r.y,im);
        r = sRhoF[xr0+yc2]; re = fmaf(s0.z,r.x,re); im = fmaf(s0.z,r.y,im);
        r = sRhoF[xr0+yc3]; re = fmaf(s0.w,r.x,re); im = fmaf(s0.w,r.y,im);
        r = sRhoF[xr1+yc0]; re = fmaf(s1.x,r.x,re); im = fmaf(s1.x,r.y,im);
        r = sRhoF[xr1+yc1]; re = fmaf(s1.y,r.x,re); im = fmaf(s1.y,r.y,im);
        r = sRhoF[xr1+yc2]; re = fmaf(s1.z,r.x,re); im = fmaf(s1.z,r.y,im);
        r = sRhoF[xr1+yc3]; re = fmaf(s1.w,r.x,re); im = fmaf(s1.w,r.y,im);
        r = sRhoF[xr2+yc0]; re = fmaf(s2.x,r.x,re); im = fmaf(s2.x,r.y,im);
        r = sRhoF[xr2+yc1]; re = fmaf(s2.y,r.x,re); im = fmaf(s2.y,r.y,im);
        r = sRhoF[xr2+yc2]; re = fmaf(s2.z,r.x,re); im = fmaf(s2.z,r.y,im);
        r = sRhoF[xr2+yc3]; re = fmaf(s2.w,r.x,re); im = fmaf(s2.w,r.y,im);
        r = sRhoF[xr3+yc0]; re = fmaf(s3.x,r.x,re); im = fmaf(s3.x,r.y,im);
        r = sRhoF[xr3+yc1]; re = fmaf(s3.y,r.x,re); im = fmaf(s3.y,r.y,im);
        r = sRhoF[xr3+yc2]; re = fmaf(s3.z,r.x,re); im = fmaf(s3.z,r.y,im);
        r = sRhoF[xr3+yc3]; re = fmaf(s3.w,r.x,re); im = fmaf(s3.w,r.y,im);
    }
    #pragma unroll
    for (int i = ct_s0(Q); i < ct_s1(Q); i++) {
        const int mi = ct_sb(i);
        int xl = (x&mi)!=0, yl = (y&mi)!=0;
        int xb0 = (x & ~mi) << 7;
        int xb1 = xb0 + (mi<<7);
        int y0 = y & ~mi;
        const float* Ss = sSsF + i*16 + (xl*2+yl)*4;
        float s0 = Ss[0], s1 = Ss[1], s2 = Ss[2], s3 = Ss[3];
        float2 r;
        r = sRhoF[xb0 + y0];      re = fmaf(s0,r.x,re); im = fmaf(s0,r.y,im);
        r = sRhoF[xb0 + y0 + mi]; re = fmaf(s1,r.x,re); im = fmaf(s1,r.y,im);
        r = sRhoF[xb1 + y0];      re = fmaf(s2,r.x,re); im = fmaf(s2,r.y,im);
        r = sRhoF[xb1 + y0 + mi]; re = fmaf(s3,r.x,re); im = fmaf(s3,r.y,im);
    }
}

// ---------------- RK4 stage combination (shared epilogue) ----------------
__device__ __forceinline__ void stage_combine(int j, int step, int idx1, int idx2, bool mirror,
                                              float re, float im,
                                              float* __restrict__ out,
                                              const float* __restrict__ t_eval)
{
    float dt = __ldg(&t_eval[step+1]) - __ldg(&t_eval[step]);
    const float2* sb = rsv(cs_sb[j]);
    float2* so = rsvw(cs_so[j]);
    float cs = cs_fs[j]*dt;
    float2 sv = __ldcg(&sb[idx1]);
    float2 ov = make_float2(fmaf(cs, re, sv.x), fmaf(cs, im, sv.y));
    so[idx1] = ov;
    if (mirror) so[idx2] = make_float2(ov.x, -ov.y);
    if (j == 3) {
        out[(step+1)*D*D + idx1] = ov.x;
        if (mirror) out[(step+1)*D*D + idx2] = ov.x;
    }
    float fa = cs_fa[j];
    if (fa != 0.f) {
        const float2* ab = rsv(cs_ab[j]);
        float2 av = __ldcg(&ab[idx1]);
        float ca = fa*dt;
        float2 acv = make_float2(fmaf(ca, re, av.x), fmaf(ca, im, av.y));
        g_acc[idx1] = acv;
        if (mirror) g_acc[idx2] = make_float2(acv.x, -acv.y);
    }
}

// ---------------- the single fused kernel ----------------
__global__ void __launch_bounds__(NTHR, 1)
solve_kernel(float* __restrict__ out, const float* __restrict__ t_eval,
             const float* __restrict__ features,
             const float* __restrict__ W1, const float* __restrict__ b1,
             const float* __restrict__ W2, const float* __restrict__ b2,
             const float* __restrict__ Hself, const float* __restrict__ Hcoup,
             const float* __restrict__ rates, const float* __restrict__ rho0)
{
    extern __shared__ __align__(16) char smem[];
    int x   = blockIdx.x;           // 0..127 normal, 128 special
    int tid = threadIdx.x;
    int q   = tid >> 6;             // 0..9, warp-uniform
    int jj  = tid & 63;
    unsigned int sense = 0;
    bool normal = (x < D);

    // ---- phase A: prep (block 0) ----
    if (x == 0)
        prep_inline(tid, smem, features, W1, b1, W2, b2, Hself, Hcoup, rates);
    grid_barrier(sense);

    // ---- phase B: build A sparse tables + init rho/out0 (blocks 0..127) ----
    if (normal && tid < D) {
        int yb = tid;
        int d = x ^ yb;
        float Hv = 0.f, Mv = 0.f;
        #pragma unroll
        for (int i = 0; i < NQ; i++) {
            int mi = 1<<(6-i);
            if ((d & (127 ^ mi)) == 0) {
                int xl = (x>>(6-i))&1, yl = (yb>>(6-i))&1;
                Hv += g_Hs1[i][xl*2+yl];
                Mv += g_Cs1[i][xl*2+yl];
            }
        }
        #pragma unroll
        for (int p = 0; p < NPAIR; p++) {
            int mi = c_mi[p], mj = c_mj[p];
            if ((d & (127 ^ (mi|mj))) == 0) {
                int xl = (((x&mi)!=0)<<1)|((x&mj)!=0);
                int yl = (((yb&mi)!=0)<<1)|((yb&mj)!=0);
                Hv += g_Hp[p][xl*4+yl];
                Mv += g_Cp[p][xl*4+yl];
            }
        }
        int k = c_lut[d];
        if (k < NOFF) {
            g_Arow[(k<<7)+x] = make_float2(-0.5f*Mv, -Hv);
            g_Acol[(k<<7)+x] = make_float2(-0.5f*Mv,  Hv);
        }
        float v = rho0[(x<<7)+yb];
        g_rho[(x<<7)+yb] = make_float2(v, 0.f);
        out[(x<<7)+yb] = v;
    }
    grid_barrier(sense);

    // ---- phase C: stage invariant tables ----
    if (normal) {
        float2* sAcol = (float2*)(smem + SM_ACOL);
        float2* sArow = (float2*)(smem + SM_AROW);
        float*  sSx   = (float*)(smem + SM_SX);
        float*  sSsx  = (float*)(smem + SM_SSX);
        {
            const float4* gv = (const float4*)g_Acol;
            float4* sv = (float4*)sAcol;
            for (int t = tid; t < NOFF*64; t += NTHR) sv[t] = __ldcg(&gv[t]);
        }
        if (tid < NOFF) sArow[tid] = __ldcg(&g_Arow[(tid<<7) + x]);
        for (int t = tid; t < NPAIR*64; t += NTHR) {
            int p = t >> 6;
            int mi = c_mi[p], mj = c_mj[p];
            int xl = (((x&mi)!=0)<<1)|((x&mj)!=0);
            sSx[t] = __ldcg(&g_Sp[p][xl*64 + (t & 63)]);
        }
        if (tid >= NTHR-NQ*8) {
            int t = tid - (NTHR-NQ*8);
            int i = t >> 3;
            int mi = 1<<(6-i);
            int xl = (x & mi) != 0;
            sSsx[t] = __ldcg(&g_Ss1[i][xl*8 + (t & 7)]);
        }
    } else {
        // special block: full tables
        float4* aR = (float4*)(smem + BF_AROW);
        float4* aC = (float4*)(smem + BF_ACOL);
        float4* sP = (float4*)(smem + BF_SP);
        float4* sS = (float4*)(smem + BF_SS);
        const float4* gR = (const float4*)g_Arow;
        const float4* gC = (const float4*)g_Acol;
        const float4* gP = (const float4*)g_Sp;
        const float4* gS = (const float4*)g_Ss1;
        for (int t = tid; t < NOFF*64; t += NTHR) { aR[t] = __ldcg(&gR[t]); aC[t] = __ldcg(&gC[t]); }
        for (int t = tid; t < NPAIR*64; t += NTHR) sP[t] = __ldcg(&gP[t]);
        if (tid < 28) sS[tid] = __ldcg(&gS[tid]);
    }

    // ---- phase D: 16 RK4 stages ----
    for (int s = 0; s < NSTAGE; s++) {
        int j = s & 3, step = s >> 2;
        const float2* in = rsv(cs_in[j]);

        if (normal) {
            float2* sRho = (float2*)(smem + SM_RHO);
            const float4* inv = (const float4*)in;
            float4* srv = (float4*)sRho;
            for (int t = tid; t < NOFF*64; t += NTHR) {
                int k = t >> 6, c4 = t & 63;
                srv[t] = __ldcg(&inv[((x ^ c_dd[k])<<6) + c4]);
            }
        } else {
            const float4* inv = (const float4*)in;
            float4* srv = (float4*)(smem + BF_RHO);
            for (int t = tid; t < D*32; t += NTHR) srv[t] = __ldcg(&inv[t]);
        }
        __syncthreads();

        if (normal) {
            const float2* sRho  = (const float2*)(smem + SM_RHO);
            const float2* sAcol = (const float2*)(smem + SM_ACOL);
            const float2* sArow = (const float2*)(smem + SM_AROW);
            const float*  sSx   = (const float*)(smem + SM_SX);
            const float*  sSsx  = (const float*)(smem + SM_SSX);
            float2* sPart = (float2*)(smem + SM_PART);
            int y = (x + jj) & 127;
            float re = 0.f, im = 0.f;
            switch (q) {
                case 0:  comp_stage<0>(sRho, sAcol, sArow, sSx, sSsx, x, y, re, im); break;
                case 1:  comp_stage<1>(sRho, sAcol, sArow, sSx, sSsx, x, y, re, im); break;
                case 2:  comp_stage<2>(sRho, sAcol, sArow, sSx, sSsx, x, y, re, im); break;
                case 3:  comp_stage<3>(sRho, sAcol, sArow, sSx, sSsx, x, y, re, im); break;
                case 4:  comp_stage<4>(sRho, sAcol, sArow, sSx, sSsx, x, y, re, im); break;
                case 5:  comp_stage<5>(sRho, sAcol, sArow, sSx, sSsx, x, y, re, im); break;
                case 6:  comp_stage<6>(sRho, sAcol, sArow, sSx, sSsx, x, y, re, im); break;
                case 7:  comp_stage<7>(sRho, sAcol, sArow, sSx, sSsx, x, y, re, im); break;
                case 8:  comp_stage<8>(sRho, sAcol, sArow, sSx, sSsx, x, y, re, im); break;
                default: comp_stage<9>(sRho, sAcol, sArow, sSx, sSsx, x, y, re, im); break;
            }
            if (q != 0) sPart[(q-1)*NCOL + jj] = make_float2(re, im);
            __syncthreads();
            if (q == 0) {
                #pragma unroll
                for (int g = 0; g < NGRP-1; g++) {
                    float2 pp = sPart[g*NCOL + jj];
                    re += pp.x; im += pp.y;
                }
                stage_combine(j, step, (x<<7)+y, (y<<7)+x, jj != 0, re, im, out, t_eval);
            }
        } else {
            const float2* sRhoF  = (const float2*)(smem + BF_RHO);
            const float2* sArowF = (const float2*)(smem + BF_AROW);
            const float2* sAcolF = (const float2*)(smem + BF_ACOL);
            const float*  sSpF   = (const float*)(smem + BF_SP);
            const float*  sSsF   = (const float*)(smem + BF_SS);
            float2* sPart = (float2*)(smem + BF_PART);
            int xe = jj, ye = jj + 64;      // the 64 anti-diagonal elements
            float re = 0.f, im = 0.f;
            switch (q) {
                case 0:  comp_full<0>(sRhoF, sArowF, sAcolF, sSpF, sSsF, xe, ye, re, im); break;
                case 1:  comp_full<1>(sRhoF, sArowF, sAcolF, sSpF, sSsF, xe, ye, re, im); break;
                case 2:  comp_full<2>(sRhoF, sArowF, sAcolF, sSpF, sSsF, xe, ye, re, im); break;
                case 3:  comp_full<3>(sRhoF, sArowF, sAcolF, sSpF, sSsF, xe, ye, re, im); break;
                case 4:  comp_full<4>(sRhoF, sArowF, sAcolF, sSpF, sSsF, xe, ye, re, im); break;
                case 5:  comp_full<5>(sRhoF, sArowF, sAcolF, sSpF, sSsF, xe, ye, re, im); break;
                case 6:  comp_full<6>(sRhoF, sArowF, sAcolF, sSpF, sSsF, xe, ye, re, im); break;
                case 7:  comp_full<7>(sRhoF, sArowF, sAcolF, sSpF, sSsF, xe, ye, re, im); break;
                case 8:  comp_full<8>(sRhoF, sArowF, sAcolF, sSpF, sSsF, xe, ye, re, im); break;
                default: comp_full<9>(sRhoF, sArowF, sAcolF, sSpF, sSsF, xe, ye, re, im); break;
            }
            if (q != 0) sPart[(q-1)*NCOL + jj] = make_float2(re, im);
            __syncthreads();
            if (q == 0) {
                #pragma unroll
                for (int g = 0; g < NGRP-1; g++) {
                    float2 pp = sPart[g*NCOL + jj];
                    re += pp.x; im += pp.y;
                }
                stage_combine(j, step, (xe<<7)+ye, (ye<<7)+xe, true, re, im, out, t_eval);
            }
        }
        grid_barrier(sense);   // 18 barriers total (even)
    }
}

// ---------------- launcher ----------------
extern "C" void kernel_launch(void* const* d_in, const int* in_sizes, int n_in,
                              void* d_out, int out_size)
{
    const float *features=0, *t_eval=0, *W1=0, *b1=0, *W2=0, *b2=0;
    const float *Hself=0, *Hcoup=0, *rates=0, *rho0=0;
    int n784 = 0;
    for (int i = 0; i < n_in; i++) {
        const float* p = (const float*)d_in[i];
        switch (in_sizes[i]) {
            case 14:    features = p; break;
            case 5:     t_eval   = p; break;
            case 128:   W1       = p; break;
            case 64:    b1       = p; break;
            case 256:   W2       = p; break;
            case 4:     b2       = p; break;
            case 28:    Hself    = p; break;
            case 784:   if (n784++ == 0) Hcoup = p; else rates = p; break;
            case 16384: rho0     = p; break;
            default: break;
        }
    }
    if (!features) features = (const float*)d_in[0];
    if (!t_eval)   t_eval   = (const float*)d_in[1];
    if (!W1)       W1       = (const float*)d_in[2];
    if (!b1)       b1       = (const float*)d_in[3];
    if (!W2)       W2       = (const float*)d_in[4];
    if (!b2)       b2       = (const float*)d_in[5];
    if (!Hself)    Hself    = (const float*)d_in[6];
    if (!Hcoup)    Hcoup    = (const float*)d_in[7];
    if (!rates)    rates    = (const float*)d_in[8];
    if (!rho0)     rho0     = (const float*)d_in[9];

    float* out = (float*)d_out;   // float32 real output, (5,128,128)

    static int attrDone = 0;
    if (!attrDone) {
        cudaFuncSetAttribute(solve_kernel, cudaFuncAttributeMaxDynamicSharedMemorySize, SMEM_BYTES);
        attrDone = 1;
    }

    solve_kernel<<<D+1, NTHR, SMEM_BYTES>>>(out, t_eval, features, W1, b1, W2, b2,
                                            Hself, Hcoup, rates, rho0);
    (void)out_size;
}